// round 11
// baseline (speedup 1.0000x reference)
#include <cuda_runtime.h>
#include <cuda_fp16.h>
#include <cstdint>

// Problem constants
#define NROWS   4096
#define INFEAT  4096
#define OUTFEAT 4096
#define NCODE   256
#define KLEAF   16
#define KGLOB   4096
// Aggregation tiling
#define TO      64
#define TN      128
#define THREADS 256
#define CCH     8
#define NCHUNK  (NCODE / CCH)      // 32
#define BUFB    16384              // bytes per staging buffer (128 idx x 64 half)
#define NBUF    3
#define AGG_SMEM (NBUF * BUFB)     // 48 KB

// Static device scratch
__device__ __align__(16) unsigned char g_codes[NROWS * NCODE];          // 1 MB
__device__ __align__(16) __half        g_lutT[(size_t)KGLOB * OUTFEAT]; // 32 MB [k][o]

// ---------------------------------------------------------------- helpers
__device__ __forceinline__ uint32_t smem_u32(const void* p) {
    uint32_t a;
    asm("{ .reg .u64 t; cvta.to.shared.u64 t, %1; cvt.u32.u64 %0, t; }"
        : "=r"(a) : "l"(p));
    return a;
}
__device__ __forceinline__ void cp_async16(uint32_t s, const void* g) {
    asm volatile("cp.async.cg.shared.global [%0], [%1], 16;"
                 :: "r"(s), "l"(g) : "memory");
}
__device__ __forceinline__ void cp_commit() {
    asm volatile("cp.async.commit_group;" ::: "memory");
}
template <int N>
__device__ __forceinline__ void cp_wait() {
    asm volatile("cp.async.wait_group %0;" :: "n"(N) : "memory");
}

// ---------------------------------------------------------------- pre
// Fused encode + transpose/convert (independent -> one launch, run
// concurrently across the grid; both are DRAM-bound).
//   blocks [0, NROWS)        : encode row n = blockIdx.x
//   blocks [NROWS, NROWS+4096): transpose 64x64 tile, linear id after NROWS
__global__ void __launch_bounds__(256) pre_kernel(
    const float* __restrict__ input,
    const int*   __restrict__ dims,
    const float* __restrict__ thr,
    const float* __restrict__ lut)
{
    __shared__ __half tile[64][66];
    const int tid = threadIdx.x;

    if (blockIdx.x < NROWS) {
        // ---------------- encode ----------------
        const int n = blockIdx.x;
        const int c = tid;
        const int4 d4 = *reinterpret_cast<const int4*>(dims + c * 4);
        const float* row = input + (size_t)n * INFEAT;
        const float x0 = __ldg(row + d4.x);
        const float x1 = __ldg(row + d4.y);
        const float x2 = __ldg(row + d4.z);
        const float x3 = __ldg(row + d4.w);
        const float* t = thr + c * 15;
        int i = 1;
        i = 2 * i + (x0 > __ldg(t + i - 1) ? 1 : 0);
        i = 2 * i + (x1 > __ldg(t + i - 1) ? 1 : 0);
        i = 2 * i + (x2 > __ldg(t + i - 1) ? 1 : 0);
        i = 2 * i + (x3 > __ldg(t + i - 1) ? 1 : 0);
        g_codes[n * NCODE + c] = (unsigned char)(i - 16);
    } else {
        // ---------------- transpose + convert ----------------
        const int linear = blockIdx.x - NROWS;      // 0..4095
        const int k0 = (linear >> 6) * 64;
        const int o0 = (linear & 63) * 64;

#pragma unroll
        for (int j = 0; j < 16; ++j) {
            const int flat = j * 256 + tid;
            const int o = flat >> 6;
            const int k = flat & 63;
            tile[k][o] = __float2half(
                __ldg(lut + (size_t)(o0 + o) * KGLOB + k0 + k));
        }
        __syncthreads();
#pragma unroll
        for (int j = 0; j < 16; ++j) {
            const int flat = j * 256 + tid;
            const int k = flat >> 6;
            const int o = flat & 63;
            g_lutT[(size_t)(k0 + k) * OUTFEAT + o0 + o] = tile[k][o];
        }
    }
}

// ---------------------------------------------------------------- agg
// Block: 256 threads (8 warps), occ 3 (48 KB smem). Tile: TO=64 x TN=128.
// 2048 blocks -> wave-tail quantization 8.4% (was 13.5% at 1024/occ2).
// Staging: cp.async, 3 buffers, distance-2 prefetch, one barrier per chunk.
// Gather: one LDS.32 per (row, cb) -- single conflict-free 128B wavefront;
// 8 loads issued up-front, depth-3 pairwise HADD2 tree, fp32 fold per chunk
// (bit-identical summation tree per output vs the R10 champion).
__global__ void __launch_bounds__(THREADS, 3) agg_kernel(float* __restrict__ out)
{
    extern __shared__ __align__(16) char smem[];
    const uint32_t sb = smem_u32(smem);

    const int o0   = blockIdx.x * TO;
    const int n0   = blockIdx.y * TN;
    const int tid  = threadIdx.x;
    const int warp = tid >> 5;
    const int lane = tid & 31;
    const int rowbase = n0 + warp * 16;

    const uint32_t lane_byte = (uint32_t)lane * 4;   // LDS.32 base in idx-row

    float acc[16][2];
#pragma unroll
    for (int t = 0; t < 16; ++t) { acc[t][0] = 0.0f; acc[t][1] = 0.0f; }

    // Stage chunk ch into buffer (1024 x 16B, 4 per thread, coalesced)
#define STAGE(ch, bufbase) do {                                                \
    const int _c0k = (ch) * CCH * KLEAF;                                       \
    _Pragma("unroll")                                                          \
    for (int _i = 0; _i < 4; ++_i) {                                           \
        const int _flat = _i * THREADS + tid;      /* 0..1023 */               \
        const int _idx  = _flat >> 3;              /* idx row, 128B each */    \
        const int _pos  = _flat & 7;                                           \
        cp_async16((bufbase) + (uint32_t)_flat * 16,                           \
                   g_lutT + (size_t)(_c0k + _idx) * OUTFEAT + o0 + _pos * 8);  \
    }                                                                          \
    cp_commit();                                                               \
} while (0)

    // Prologue: prefetch chunks 0 and 1
    STAGE(0, sb);
    STAGE(1, sb + BUFB);

    for (int ch = 0; ch < NCHUNK; ++ch) {
        if (ch + 1 < NCHUNK) cp_wait<1>();
        else                 cp_wait<0>();
        __syncthreads();   // chunk ch visible; buffer (ch+2)%3 drained

        if (ch + 2 < NCHUNK)
            STAGE(ch + 2, sb + (uint32_t)((ch + 2) % NBUF) * BUFB);

        const uint32_t gbase = sb + (uint32_t)(ch % NBUF) * BUFB + lane_byte;
        const int cb0 = ch * CCH;

#pragma unroll
        for (int t = 0; t < 16; ++t) {
            const int row = rowbase + t;
            const uint2 cw = *reinterpret_cast<const uint2*>(
                g_codes + (size_t)row * NCODE + cb0);   // warp-uniform

            uint32_t v[8];
#pragma unroll
            for (int cc = 0; cc < 8; ++cc) {
                const unsigned int w = (cc < 4) ? cw.x : cw.y;
                const unsigned int code = (w >> (8 * (cc & 3))) & 0xFFu;
                // row (cc*16 + code) at 128B stride: cc*2048 folds into the
                // LDS immediate after unroll; code<<7 is one LEA.
                const uint32_t a = gbase + (uint32_t)cc * 2048u + (code << 7);
                asm volatile("ld.shared.u32 %0, [%1];" : "=r"(v[cc]) : "r"(a));
            }
#define H2(x) (*reinterpret_cast<const __half2*>(&(x)))
            // Pairwise reduction, depth 3 (same tree as R10 champion)
            const __half2 p0 = __hadd2(H2(v[0]), H2(v[1]));
            const __half2 p1 = __hadd2(H2(v[2]), H2(v[3]));
            const __half2 p2 = __hadd2(H2(v[4]), H2(v[5]));
            const __half2 p3 = __hadd2(H2(v[6]), H2(v[7]));
            const __half2 h  = __hadd2(__hadd2(p0, p1), __hadd2(p2, p3));
#undef H2
            const float2 f = __half22float2(h);
            acc[t][0] += f.x;
            acc[t][1] += f.y;
        }
    }

    // Store: coalesced float2 writes (32 lanes x 8B = 256B per row)
#pragma unroll
    for (int t = 0; t < 16; ++t) {
        float2 a; a.x = acc[t][0]; a.y = acc[t][1];
        *reinterpret_cast<float2*>(
            out + (size_t)(rowbase + t) * OUTFEAT + o0 + 2 * lane) = a;
    }
}

// ---------------------------------------------------------------- launch
extern "C" void kernel_launch(void* const* d_in, const int* in_sizes, int n_in,
                              void* d_out, int out_size)
{
    const float* input = (const float*)d_in[0];
    const int*   dims  = (const int*)  d_in[1];
    const float* thr   = (const float*)d_in[3];
    const float* lut   = (const float*)d_in[5];
    float*       out   = (float*)d_out;
    (void)in_sizes; (void)n_in; (void)out_size;

    cudaFuncSetAttribute(agg_kernel,
                         cudaFuncAttributeMaxDynamicSharedMemorySize, AGG_SMEM);

    // Fused encode + lut transpose/convert (independent halves of the grid)
    pre_kernel<<<NROWS + (KGLOB / 64) * (OUTFEAT / 64), 256>>>(
        input, dims, thr, lut);

    dim3 grid(OUTFEAT / TO, NROWS / TN);
    agg_kernel<<<grid, THREADS, AGG_SMEM>>>(out);
}

// round 12
// speedup vs baseline: 1.1757x; 1.1757x over previous
#include <cuda_runtime.h>
#include <cuda_fp16.h>
#include <cstdint>

// Problem constants
#define NROWS   4096
#define INFEAT  4096
#define OUTFEAT 4096
#define NCODE   256
#define KLEAF   16
#define KGLOB   4096
// Aggregation tiling
#define TO      128
#define TN      64
#define THREADS 256
#define CCH     8
#define NCHUNK  (NCODE / CCH)      // 32
#define BUFB    32768              // bytes per staging buffer (128 idx x 128 half)
#define NBUF    3
#define AGG_SMEM (NBUF * BUFB)     // 96 KB

// Static device scratch
__device__ __align__(16) unsigned char g_codes[NROWS * NCODE];          // 1 MB
__device__ __align__(16) __half        g_lutT[(size_t)KGLOB * OUTFEAT]; // 32 MB [k][o]

// ---------------------------------------------------------------- helpers
__device__ __forceinline__ uint32_t smem_u32(const void* p) {
    uint32_t a;
    asm("{ .reg .u64 t; cvta.to.shared.u64 t, %1; cvt.u32.u64 %0, t; }"
        : "=r"(a) : "l"(p));
    return a;
}
__device__ __forceinline__ void cp_async16(uint32_t s, const void* g) {
    asm volatile("cp.async.cg.shared.global [%0], [%1], 16;"
                 :: "r"(s), "l"(g) : "memory");
}
__device__ __forceinline__ void cp_commit() {
    asm volatile("cp.async.commit_group;" ::: "memory");
}
template <int N>
__device__ __forceinline__ void cp_wait() {
    asm volatile("cp.async.wait_group %0;" :: "n"(N) : "memory");
}

// ---------------------------------------------------------------- pre
// Fused encode + transpose/convert (independent halves of one grid).
__global__ void __launch_bounds__(256) pre_kernel(
    const float* __restrict__ input,
    const int*   __restrict__ dims,
    const float* __restrict__ thr,
    const float* __restrict__ lut)
{
    __shared__ __half tile[64][66];
    const int tid = threadIdx.x;

    if (blockIdx.x < NROWS) {
        // ---------------- encode ----------------
        const int n = blockIdx.x;
        const int c = tid;
        const int4 d4 = *reinterpret_cast<const int4*>(dims + c * 4);
        const float* row = input + (size_t)n * INFEAT;
        const float x0 = __ldg(row + d4.x);
        const float x1 = __ldg(row + d4.y);
        const float x2 = __ldg(row + d4.z);
        const float x3 = __ldg(row + d4.w);
        const float* t = thr + c * 15;
        int i = 1;
        i = 2 * i + (x0 > __ldg(t + i - 1) ? 1 : 0);
        i = 2 * i + (x1 > __ldg(t + i - 1) ? 1 : 0);
        i = 2 * i + (x2 > __ldg(t + i - 1) ? 1 : 0);
        i = 2 * i + (x3 > __ldg(t + i - 1) ? 1 : 0);
        g_codes[n * NCODE + c] = (unsigned char)(i - 16);
    } else {
        // ---------------- transpose + convert ----------------
        const int linear = blockIdx.x - NROWS;      // 0..4095
        const int k0 = (linear >> 6) * 64;
        const int o0 = (linear & 63) * 64;

#pragma unroll
        for (int j = 0; j < 16; ++j) {
            const int flat = j * 256 + tid;
            const int o = flat >> 6;
            const int k = flat & 63;
            tile[k][o] = __float2half(
                __ldg(lut + (size_t)(o0 + o) * KGLOB + k0 + k));
        }
        __syncthreads();
#pragma unroll
        for (int j = 0; j < 16; ++j) {
            const int flat = j * 256 + tid;
            const int k = flat >> 6;
            const int o = flat & 63;
            g_lutT[(size_t)(k0 + k) * OUTFEAT + o0 + o] = tile[k][o];
        }
    }
}

// ---------------------------------------------------------------- agg
// R10 champion structure with TN=64 (tail fix):
// Block: 256 threads (8 warps), occ 2. Tile: TO=128 outputs x TN=64 rows.
// 2048 blocks / 296 occ-2 slots = 6.92 waves -> 1.2% tail (was 13.5%).
// Per-lane economics unchanged from R10: 2 LDS.32 feed 4 outputs.
// Staging: cp.async, 3 buffers, distance-2 prefetch, one barrier per chunk.
// Depth-3 pairwise HADD2 tree, fp32 fold per chunk (bit-identical per-output
// summation vs R10 -> rel_err 4.4163e-4).
__global__ void __launch_bounds__(THREADS, 2) agg_kernel(float* __restrict__ out)
{
    extern __shared__ __align__(16) char smem[];
    const uint32_t sb = smem_u32(smem);

    const int o0   = blockIdx.x * TO;
    const int n0   = blockIdx.y * TN;
    const int tid  = threadIdx.x;
    const int warp = tid >> 5;
    const int lane = tid & 31;
    const int rowbase = n0 + warp * 8;

    const uint32_t lane_byte = (uint32_t)lane * 4;   // LDS.32 base in idx-row

    float acc[8][4];
#pragma unroll
    for (int t = 0; t < 8; ++t)
#pragma unroll
        for (int j = 0; j < 4; ++j) acc[t][j] = 0.0f;

    // Stage chunk ch into buffer (2048 x 16B, 8 per thread, coalesced)
#define STAGE(ch, bufbase) do {                                                \
    const int _c0k = (ch) * CCH * KLEAF;                                       \
    _Pragma("unroll")                                                          \
    for (int _i = 0; _i < 8; ++_i) {                                           \
        const int _flat = _i * THREADS + tid;      /* 0..2047 */               \
        const int _idx  = _flat >> 4;                                          \
        const int _pos  = _flat & 15;                                          \
        cp_async16((bufbase) + (uint32_t)_flat * 16,                           \
                   g_lutT + (size_t)(_c0k + _idx) * OUTFEAT + o0 + _pos * 8);  \
    }                                                                          \
    cp_commit();                                                               \
} while (0)

    // Prologue: prefetch chunks 0 and 1
    STAGE(0, sb);
    STAGE(1, sb + BUFB);

    for (int ch = 0; ch < NCHUNK; ++ch) {
        if (ch + 1 < NCHUNK) cp_wait<1>();
        else                 cp_wait<0>();
        __syncthreads();   // chunk ch visible; buffer (ch+2)%3 drained

        if (ch + 2 < NCHUNK)
            STAGE(ch + 2, sb + (uint32_t)((ch + 2) % NBUF) * BUFB);

        const uint32_t gbase = sb + (uint32_t)(ch % NBUF) * BUFB + lane_byte;
        const int cb0 = ch * CCH;

#pragma unroll
        for (int t = 0; t < 8; ++t) {
            const int row = rowbase + t;
            const uint2 cw = *reinterpret_cast<const uint2*>(
                g_codes + (size_t)row * NCODE + cb0);   // warp-uniform

            uint32_t v0[8], v1[8];
#pragma unroll
            for (int cc = 0; cc < 8; ++cc) {
                const unsigned int w = (cc < 4) ? cw.x : cw.y;
                // byte (cc&3) of w placed at result byte1 => code*256
                const unsigned int c256 =
                    __byte_perm(w, 0u, 0x4404u | (((unsigned)cc & 3u) << 4));
                const uint32_t a = gbase + (uint32_t)cc * 4096u + c256;
                asm volatile("ld.shared.u32 %0, [%1];" : "=r"(v0[cc]) : "r"(a));
                asm volatile("ld.shared.u32 %0, [%1];" : "=r"(v1[cc]) : "r"(a + 128u));
            }
#define H2(x) (*reinterpret_cast<const __half2*>(&(x)))
            // Pairwise reduction, depth 3
            const __half2 p0 = __hadd2(H2(v0[0]), H2(v0[1]));
            const __half2 p1 = __hadd2(H2(v0[2]), H2(v0[3]));
            const __half2 p2 = __hadd2(H2(v0[4]), H2(v0[5]));
            const __half2 p3 = __hadd2(H2(v0[6]), H2(v0[7]));
            const __half2 q0 = __hadd2(H2(v1[0]), H2(v1[1]));
            const __half2 q1 = __hadd2(H2(v1[2]), H2(v1[3]));
            const __half2 q2 = __hadd2(H2(v1[4]), H2(v1[5]));
            const __half2 q3 = __hadd2(H2(v1[6]), H2(v1[7]));
            const __half2 h01 = __hadd2(__hadd2(p0, p1), __hadd2(p2, p3));
            const __half2 h23 = __hadd2(__hadd2(q0, q1), __hadd2(q2, q3));
#undef H2
            const float2 f0 = __half22float2(h01);
            const float2 f1 = __half22float2(h23);
            acc[t][0] += f0.x;
            acc[t][1] += f0.y;
            acc[t][2] += f1.x;
            acc[t][3] += f1.y;
        }
    }

    // Store: coalesced float2 writes
#pragma unroll
    for (int t = 0; t < 8; ++t) {
        float* orow = out + (size_t)(rowbase + t) * OUTFEAT + o0;
        float2 a; a.x = acc[t][0]; a.y = acc[t][1];
        float2 b; b.x = acc[t][2]; b.y = acc[t][3];
        *reinterpret_cast<float2*>(orow + 2 * lane)      = a;
        *reinterpret_cast<float2*>(orow + 64 + 2 * lane) = b;
    }
}

// ---------------------------------------------------------------- launch
extern "C" void kernel_launch(void* const* d_in, const int* in_sizes, int n_in,
                              void* d_out, int out_size)
{
    const float* input = (const float*)d_in[0];
    const int*   dims  = (const int*)  d_in[1];
    const float* thr   = (const float*)d_in[3];
    const float* lut   = (const float*)d_in[5];
    float*       out   = (float*)d_out;
    (void)in_sizes; (void)n_in; (void)out_size;

    cudaFuncSetAttribute(agg_kernel,
                         cudaFuncAttributeMaxDynamicSharedMemorySize, AGG_SMEM);

    pre_kernel<<<NROWS + (KGLOB / 64) * (OUTFEAT / 64), 256>>>(
        input, dims, thr, lut);

    dim3 grid(OUTFEAT / TO, NROWS / TN);
    agg_kernel<<<grid, THREADS, AGG_SMEM>>>(out);
}

// round 13
// speedup vs baseline: 1.3616x; 1.1582x over previous
#include <cuda_runtime.h>
#include <cuda_fp16.h>
#include <cstdint>

// Problem constants
#define NROWS   4096
#define INFEAT  4096
#define OUTFEAT 4096
#define NCODE   256
#define KLEAF   16
#define KGLOB   4096
// Aggregation tiling (R10 economics: fixed by R11/R12 experiments)
#define TO      128
#define TN      128
#define THREADS 256
#define CCH     8
#define NCHUNK  (NCODE / CCH)      // 32
#define BUFB    32768              // 128 idx rows x 256 B
#define NBUF    3
#define AGG_SMEM (NBUF * BUFB)     // 96 KB

// Static device scratch
__device__ __align__(16) unsigned char g_codes[NROWS * NCODE];          // 1 MB
__device__ __align__(16) __half        g_lutT[(size_t)KGLOB * OUTFEAT]; // 32 MB [k][o]

// ---------------------------------------------------------------- helpers
__device__ __forceinline__ uint32_t smem_u32(const void* p) {
    uint32_t a;
    asm("{ .reg .u64 t; cvta.to.shared.u64 t, %1; cvt.u32.u64 %0, t; }"
        : "=r"(a) : "l"(p));
    return a;
}
__device__ __forceinline__ void cp_async16(uint32_t s, const void* g) {
    asm volatile("cp.async.cg.shared.global [%0], [%1], 16;"
                 :: "r"(s), "l"(g) : "memory");
}
__device__ __forceinline__ void cp_commit() {
    asm volatile("cp.async.commit_group;" ::: "memory");
}
template <int N>
__device__ __forceinline__ void cp_wait() {
    asm volatile("cp.async.wait_group %0;" :: "n"(N) : "memory");
}

// ---------------------------------------------------------------- pre
// Fused encode + transpose/convert (independent halves of one grid).
__global__ void __launch_bounds__(256) pre_kernel(
    const float* __restrict__ input,
    const int*   __restrict__ dims,
    const float* __restrict__ thr,
    const float* __restrict__ lut)
{
    __shared__ __half tile[64][72];   // 144B row stride: 16B-aligned, low conflict
    const int tid = threadIdx.x;

    if (blockIdx.x < NROWS) {
        // ---------------- encode ----------------
        const int n = blockIdx.x;
        const int c = tid;
        const int4 d4 = *reinterpret_cast<const int4*>(dims + c * 4);
        const float* row = input + (size_t)n * INFEAT;
        const float x0 = __ldg(row + d4.x);
        const float x1 = __ldg(row + d4.y);
        const float x2 = __ldg(row + d4.z);
        const float x3 = __ldg(row + d4.w);
        const float* t = thr + c * 15;
        int i = 1;
        i = 2 * i + (x0 > __ldg(t + i - 1) ? 1 : 0);
        i = 2 * i + (x1 > __ldg(t + i - 1) ? 1 : 0);
        i = 2 * i + (x2 > __ldg(t + i - 1) ? 1 : 0);
        i = 2 * i + (x3 > __ldg(t + i - 1) ? 1 : 0);
        g_codes[n * NCODE + c] = (unsigned char)(i - 16);
    } else {
        // -------- transpose + convert (vectorized) --------
        const int linear = blockIdx.x - NROWS;      // 0..4095
        const int k0 = (linear >> 6) * 64;
        const int o0 = (linear & 63) * 64;

        // Load: 64 o-rows x 16 float4 (k-contiguous), 4 iters x 256 thr
#pragma unroll
        for (int j = 0; j < 4; ++j) {
            const int flat = j * 256 + tid;          // 0..1023
            const int o  = flat >> 4;
            const int kq = flat & 15;                // float4 index along k
            const float4 v = __ldg(reinterpret_cast<const float4*>(
                lut + (size_t)(o0 + o) * KGLOB + k0 + kq * 4));
            tile[kq * 4 + 0][o] = __float2half(v.x);
            tile[kq * 4 + 1][o] = __float2half(v.y);
            tile[kq * 4 + 2][o] = __float2half(v.z);
            tile[kq * 4 + 3][o] = __float2half(v.w);
        }
        __syncthreads();

        // Store: 64 k-rows x 8 uint4 (o-contiguous), 2 iters x 256 thr
#pragma unroll
        for (int j = 0; j < 2; ++j) {
            const int flat = j * 256 + tid;          // 0..511
            const int k  = flat >> 3;
            const int oq = flat & 7;                 // uint4 index along o
            const uint4 v = *reinterpret_cast<const uint4*>(&tile[k][oq * 8]);
            *reinterpret_cast<uint4*>(
                g_lutT + (size_t)(k0 + k) * OUTFEAT + o0 + oq * 8) = v;
        }
    }
}

// ---------------------------------------------------------------- agg
// R10 champion + LDS.64 gathers (R7 vs R8 showed 64-bit shared loads carry
// no replay tax; saves 8 MIO issue slots per row).
// Block: 256 threads (8 warps), occ 2. Tile: TO=128 outputs x TN=128 rows.
// Lane owns outputs {4l..4l+3} at byte 8l of each idx-row -> one aligned
// LDS.64 per (row, codebook), two conflict-free 128B wavefronts.
// Staging: cp.async, 3 buffers, distance-2 prefetch, one barrier per chunk.
// Depth-3 pairwise HADD2 tree per half2, fp32 fold per chunk — per-output
// summation bit-identical to R10 (rel_err 4.4163e-4).
__global__ void __launch_bounds__(THREADS, 2) agg_kernel(float* __restrict__ out)
{
    extern __shared__ __align__(16) char smem[];
    const uint32_t sb = smem_u32(smem);

    const int o0   = blockIdx.x * TO;
    const int n0   = blockIdx.y * TN;
    const int tid  = threadIdx.x;
    const int warp = tid >> 5;
    const int lane = tid & 31;
    const int rowbase = n0 + warp * 16;

    const uint32_t lane_byte = (uint32_t)lane * 8;   // LDS.64 base in idx-row

    float acc[16][4];
#pragma unroll
    for (int t = 0; t < 16; ++t)
#pragma unroll
        for (int j = 0; j < 4; ++j) acc[t][j] = 0.0f;

    // Stage chunk ch into buffer (2048 x 16B, 8 per thread, coalesced)
#define STAGE(ch, bufbase) do {                                                \
    const int _c0k = (ch) * CCH * KLEAF;                                       \
    _Pragma("unroll")                                                          \
    for (int _i = 0; _i < 8; ++_i) {                                           \
        const int _flat = _i * THREADS + tid;      /* 0..2047 */               \
        const int _idx  = _flat >> 4;                                          \
        const int _pos  = _flat & 15;                                          \
        cp_async16((bufbase) + (uint32_t)_flat * 16,                           \
                   g_lutT + (size_t)(_c0k + _idx) * OUTFEAT + o0 + _pos * 8);  \
    }                                                                          \
    cp_commit();                                                               \
} while (0)

    // Prologue: prefetch chunks 0 and 1
    STAGE(0, sb);
    STAGE(1, sb + BUFB);

    for (int ch = 0; ch < NCHUNK; ++ch) {
        if (ch + 1 < NCHUNK) cp_wait<1>();
        else                 cp_wait<0>();
        __syncthreads();   // chunk ch visible; buffer (ch+2)%3 drained

        if (ch + 2 < NCHUNK)
            STAGE(ch + 2, sb + (uint32_t)((ch + 2) % NBUF) * BUFB);

        const uint32_t gbase = sb + (uint32_t)(ch % NBUF) * BUFB + lane_byte;
        const int cb0 = ch * CCH;

#pragma unroll
        for (int t = 0; t < 16; ++t) {
            const int row = rowbase + t;
            const uint2 cw = *reinterpret_cast<const uint2*>(
                g_codes + (size_t)row * NCODE + cb0);   // warp-uniform

            uint2 v[8];
#pragma unroll
            for (int cc = 0; cc < 8; ++cc) {
                const unsigned int w = (cc < 4) ? cw.x : cw.y;
                // byte (cc&3) of w placed at result byte1 => code*256
                const unsigned int c256 =
                    __byte_perm(w, 0u, 0x4404u | (((unsigned)cc & 3u) << 4));
                asm volatile("ld.shared.v2.u32 {%0,%1}, [%2];"
                             : "=r"(v[cc].x), "=r"(v[cc].y)
                             : "r"(gbase + (uint32_t)cc * 4096u + c256));
            }
#define H2X(i) (*reinterpret_cast<const __half2*>(&v[i].x))
#define H2Y(i) (*reinterpret_cast<const __half2*>(&v[i].y))
            // Pairwise reduction, depth 3 (same per-output tree as R10)
            const __half2 p0 = __hadd2(H2X(0), H2X(1));
            const __half2 p1 = __hadd2(H2X(2), H2X(3));
            const __half2 p2 = __hadd2(H2X(4), H2X(5));
            const __half2 p3 = __hadd2(H2X(6), H2X(7));
            const __half2 q0 = __hadd2(H2Y(0), H2Y(1));
            const __half2 q1 = __hadd2(H2Y(2), H2Y(3));
            const __half2 q2 = __hadd2(H2Y(4), H2Y(5));
            const __half2 q3 = __hadd2(H2Y(6), H2Y(7));
            const __half2 h01 = __hadd2(__hadd2(p0, p1), __hadd2(p2, p3));
            const __half2 h23 = __hadd2(__hadd2(q0, q1), __hadd2(q2, q3));
#undef H2X
#undef H2Y
            const float2 f0 = __half22float2(h01);
            const float2 f1 = __half22float2(h23);
            acc[t][0] += f0.x;
            acc[t][1] += f0.y;
            acc[t][2] += f1.x;
            acc[t][3] += f1.y;
        }
    }

    // Store: lane's 4 outputs contiguous -> STG.128 coalesced
#pragma unroll
    for (int t = 0; t < 16; ++t) {
        float4 v;
        v.x = acc[t][0]; v.y = acc[t][1]; v.z = acc[t][2]; v.w = acc[t][3];
        *reinterpret_cast<float4*>(
            out + (size_t)(rowbase + t) * OUTFEAT + o0 + 4 * lane) = v;
    }
}

// ---------------------------------------------------------------- launch
extern "C" void kernel_launch(void* const* d_in, const int* in_sizes, int n_in,
                              void* d_out, int out_size)
{
    const float* input = (const float*)d_in[0];
    const int*   dims  = (const int*)  d_in[1];
    const float* thr   = (const float*)d_in[3];
    const float* lut   = (const float*)d_in[5];
    float*       out   = (float*)d_out;
    (void)in_sizes; (void)n_in; (void)out_size;

    cudaFuncSetAttribute(agg_kernel,
                         cudaFuncAttributeMaxDynamicSharedMemorySize, AGG_SMEM);

    pre_kernel<<<NROWS + (KGLOB / 64) * (OUTFEAT / 64), 256>>>(
        input, dims, thr, lut);

    dim3 grid(OUTFEAT / TO, NROWS / TN);
    agg_kernel<<<grid, THREADS, AGG_SMEM>>>(out);
}

// round 15
// speedup vs baseline: 1.4878x; 1.0927x over previous
#include <cuda_runtime.h>
#include <cuda_fp16.h>
#include <cstdint>

// Problem constants
#define NROWS   4096
#define INFEAT  4096
#define OUTFEAT 4096
#define NCODE   256
#define KLEAF   16
#define KGLOB   4096
// Aggregation tiling (economics fixed by R11/R12/R13)
#define TO      128
#define TN      128
#define THREADS 256
#define CCH     8
#define NCHUNK  (NCODE / CCH)      // 32
#define BUFB    32768              // 128 idx rows x 256 B
#define NBUF    3
#define MBAR_OFF (NBUF * BUFB)
#define AGG_SMEM (MBAR_OFF + 64)   // 96 KB + mbarriers

// Static device scratch
__device__ __align__(16) unsigned char g_codes[NROWS * NCODE];          // 1 MB
__device__ __align__(16) __half        g_lutT[(size_t)KGLOB * OUTFEAT]; // 32 MB [k][o]

// ---------------------------------------------------------------- helpers
__device__ __forceinline__ uint32_t smem_u32(const void* p) {
    uint32_t a;
    asm("{ .reg .u64 t; cvta.to.shared.u64 t, %1; cvt.u32.u64 %0, t; }"
        : "=r"(a) : "l"(p));
    return a;
}
__device__ __forceinline__ void cp_async16(uint32_t s, const void* g) {
    asm volatile("cp.async.cg.shared.global [%0], [%1], 16;"
                 :: "r"(s), "l"(g) : "memory");
}
__device__ __forceinline__ void cp_arrive_noinc(uint32_t mbar) {
    // arrive (no expected-count increment) once this thread's prior
    // cp.asyncs have completed. Pairs with init count = THREADS.
    asm volatile("cp.async.mbarrier.arrive.noinc.shared::cta.b64 [%0];"
                 :: "r"(mbar) : "memory");
}
__device__ __forceinline__ void mbar_init(uint32_t a, uint32_t n) {
    asm volatile("mbarrier.init.shared.b64 [%0], %1;" :: "r"(a), "r"(n) : "memory");
}
__device__ __forceinline__ void mbar_arrive(uint32_t a) {
    asm volatile("mbarrier.arrive.shared.b64 _, [%0];" :: "r"(a) : "memory");
}
__device__ __forceinline__ void mbar_wait(uint32_t mbar, uint32_t parity) {
    uint32_t done;
    asm volatile(
        "{ .reg .pred p;"
        "mbarrier.try_wait.parity.acquire.cta.shared::cta.b64 p, [%1], %2;"
        "selp.b32 %0,1,0,p; }" : "=r"(done) : "r"(mbar), "r"(parity) : "memory");
    if (!done) {
        asm volatile(
            "{ .reg .pred P1; WL_%=:"
            "mbarrier.try_wait.parity.acquire.cta.shared::cta.b64 P1, [%0], %1, 0x989680;"
            "@P1 bra.uni WD_%=; bra.uni WL_%=; WD_%=: }"
            :: "r"(mbar), "r"(parity) : "memory");
    }
}

// ---------------------------------------------------------------- pre
// Fused encode + transpose/convert (independent halves of one grid).
__global__ void __launch_bounds__(256) pre_kernel(
    const float* __restrict__ input,
    const int*   __restrict__ dims,
    const float* __restrict__ thr,
    const float* __restrict__ lut)
{
    __shared__ __half tile[64][72];
    const int tid = threadIdx.x;

    if (blockIdx.x < NROWS) {
        // ---------------- encode ----------------
        const int n = blockIdx.x;
        const int c = tid;
        const int4 d4 = *reinterpret_cast<const int4*>(dims + c * 4);
        const float* row = input + (size_t)n * INFEAT;
        const float x0 = __ldg(row + d4.x);
        const float x1 = __ldg(row + d4.y);
        const float x2 = __ldg(row + d4.z);
        const float x3 = __ldg(row + d4.w);
        const float* t = thr + c * 15;
        int i = 1;
        i = 2 * i + (x0 > __ldg(t + i - 1) ? 1 : 0);
        i = 2 * i + (x1 > __ldg(t + i - 1) ? 1 : 0);
        i = 2 * i + (x2 > __ldg(t + i - 1) ? 1 : 0);
        i = 2 * i + (x3 > __ldg(t + i - 1) ? 1 : 0);
        g_codes[n * NCODE + c] = (unsigned char)(i - 16);
    } else {
        // -------- transpose + convert (vectorized) --------
        const int linear = blockIdx.x - NROWS;      // 0..4095
        const int k0 = (linear >> 6) * 64;
        const int o0 = (linear & 63) * 64;

#pragma unroll
        for (int j = 0; j < 4; ++j) {
            const int flat = j * 256 + tid;
            const int o  = flat >> 4;
            const int kq = flat & 15;
            const float4 v = __ldg(reinterpret_cast<const float4*>(
                lut + (size_t)(o0 + o) * KGLOB + k0 + kq * 4));
            tile[kq * 4 + 0][o] = __float2half(v.x);
            tile[kq * 4 + 1][o] = __float2half(v.y);
            tile[kq * 4 + 2][o] = __float2half(v.z);
            tile[kq * 4 + 3][o] = __float2half(v.w);
        }
        __syncthreads();
#pragma unroll
        for (int j = 0; j < 2; ++j) {
            const int flat = j * 256 + tid;
            const int k  = flat >> 3;
            const int oq = flat & 7;
            const uint4 v = *reinterpret_cast<const uint4*>(&tile[k][oq * 8]);
            *reinterpret_cast<uint4*>(
                g_lutT + (size_t)(k0 + k) * OUTFEAT + o0 + oq * 8) = v;
        }
    }
}

// ---------------------------------------------------------------- agg
// R13 gather/staging with an mbarrier ring in place of per-chunk block
// barriers. full[i]: 256 noinc cp.async arrivals. empty[i]: 8 warp arrivals.
// Deferred refill: after gathering chunk ch, a warp services the refill owed
// for buffer b(ch-1) (-> chunk ch-1+3), so fast warps run a chunk ahead
// before waiting on stragglers. Summation bit-identical to R13.
__global__ void __launch_bounds__(THREADS, 2) agg_kernel(float* __restrict__ out)
{
    extern __shared__ __align__(16) char smem[];
    const uint32_t sb = smem_u32(smem);
    const uint32_t MB = sb + MBAR_OFF;   // full[i]=MB+8i, empty[i]=MB+24+8i

    const int o0   = blockIdx.x * TO;
    const int n0   = blockIdx.y * TN;
    const int tid  = threadIdx.x;
    const int warp = tid >> 5;
    const int lane = tid & 31;
    const int rowbase = n0 + warp * 16;

    const uint32_t lane_byte = (uint32_t)lane * 8;   // LDS.64 base in idx-row

    if (tid == 0) {
#pragma unroll
        for (int i = 0; i < NBUF; ++i) {
            mbar_init(MB + i * 8, THREADS);   // full: noinc arrive per thread
            mbar_init(MB + 24 + i * 8, 8);    // empty: one arrive per warp
        }
    }
    __syncthreads();   // mbarriers visible before any arrive

    float acc[16][4];
#pragma unroll
    for (int t = 0; t < 16; ++t)
#pragma unroll
        for (int j = 0; j < 4; ++j) acc[t][j] = 0.0f;

    // Stage chunk ch into buffer (2048 x 16B, 8 per thread, coalesced)
#define STAGE(ch, bufbase) do {                                                \
    const int _c0k = (ch) * CCH * KLEAF;                                       \
    _Pragma("unroll")                                                          \
    for (int _i = 0; _i < 8; ++_i) {                                           \
        const int _flat = _i * THREADS + tid;      /* 0..2047 */               \
        const int _idx  = _flat >> 4;                                          \
        const int _pos  = _flat & 15;                                          \
        cp_async16((bufbase) + (uint32_t)_flat * 16,                           \
                   g_lutT + (size_t)(_c0k + _idx) * OUTFEAT + o0 + _pos * 8);  \
    }                                                                          \
} while (0)

    // Prologue: stage chunks 0..2, noinc-arrive their full barriers
#pragma unroll
    for (int p = 0; p < NBUF; ++p) {
        STAGE(p, sb + (uint32_t)p * BUFB);
        cp_arrive_noinc(MB + p * 8);
    }

    for (int ch = 0; ch < NCHUNK; ++ch) {
        const int b  = ch % NBUF;
        const uint32_t ph = (uint32_t)(ch / NBUF) & 1u;

        mbar_wait(MB + b * 8, ph);   // full[b]: round (ch/NBUF) complete

        const uint32_t gbase = sb + (uint32_t)b * BUFB + lane_byte;
        const int cb0 = ch * CCH;

#pragma unroll
        for (int t = 0; t < 16; ++t) {
            const int row = rowbase + t;
            const uint2 cw = *reinterpret_cast<const uint2*>(
                g_codes + (size_t)row * NCODE + cb0);   // warp-uniform

            uint2 v[8];
#pragma unroll
            for (int cc = 0; cc < 8; ++cc) {
                const unsigned int w = (cc < 4) ? cw.x : cw.y;
                const unsigned int c256 =
                    __byte_perm(w, 0u, 0x4404u | (((unsigned)cc & 3u) << 4));
                asm volatile("ld.shared.v2.u32 {%0,%1}, [%2];"
                             : "=r"(v[cc].x), "=r"(v[cc].y)
                             : "r"(gbase + (uint32_t)cc * 4096u + c256));
            }
#define H2X(i) (*reinterpret_cast<const __half2*>(&v[i].x))
#define H2Y(i) (*reinterpret_cast<const __half2*>(&v[i].y))
            const __half2 p0 = __hadd2(H2X(0), H2X(1));
            const __half2 p1 = __hadd2(H2X(2), H2X(3));
            const __half2 p2 = __hadd2(H2X(4), H2X(5));
            const __half2 p3 = __hadd2(H2X(6), H2X(7));
            const __half2 q0 = __hadd2(H2Y(0), H2Y(1));
            const __half2 q1 = __hadd2(H2Y(2), H2Y(3));
            const __half2 q2 = __hadd2(H2Y(4), H2Y(5));
            const __half2 q3 = __hadd2(H2Y(6), H2Y(7));
            const __half2 h01 = __hadd2(__hadd2(p0, p1), __hadd2(p2, p3));
            const __half2 h23 = __hadd2(__hadd2(q0, q1), __hadd2(q2, q3));
#undef H2X
#undef H2Y
            const float2 f0 = __half22float2(h01);
            const float2 f1 = __half22float2(h23);
            acc[t][0] += f0.x;
            acc[t][1] += f0.y;
            acc[t][2] += f1.x;
            acc[t][3] += f1.y;
        }

        if (lane == 0) mbar_arrive(MB + 24 + b * 8);   // release buffer b

        // Deferred refill: service buffer b(ch-1) -> chunk ch-1+NBUF.
        // Its empty barrier completes once all warps finished chunk ch-1,
        // which every warp has by now (it just gathered ch).
        const int pc = ch - 1;
        if (pc >= 0 && pc + NBUF < NCHUNK) {
            const int pb = pc % NBUF;
            const uint32_t pph = (uint32_t)(pc / NBUF) & 1u;
            mbar_wait(MB + 24 + pb * 8, pph);          // empty[pb]
            STAGE(pc + NBUF, sb + (uint32_t)pb * BUFB);
            cp_arrive_noinc(MB + pb * 8);
        }
    }

    // Store: lane's 4 outputs contiguous -> STG.128 coalesced
#pragma unroll
    for (int t = 0; t < 16; ++t) {
        float4 v;
        v.x = acc[t][0]; v.y = acc[t][1]; v.z = acc[t][2]; v.w = acc[t][3];
        *reinterpret_cast<float4*>(
            out + (size_t)(rowbase + t) * OUTFEAT + o0 + 4 * lane) = v;
    }
}

// ---------------------------------------------------------------- launch
extern "C" void kernel_launch(void* const* d_in, const int* in_sizes, int n_in,
                              void* d_out, int out_size)
{
    const float* input = (const float*)d_in[0];
    const int*   dims  = (const int*)  d_in[1];
    const float* thr   = (const float*)d_in[3];
    const float* lut   = (const float*)d_in[5];
    float*       out   = (float*)d_out;
    (void)in_sizes; (void)n_in; (void)out_size;

    cudaFuncSetAttribute(agg_kernel,
                         cudaFuncAttributeMaxDynamicSharedMemorySize, AGG_SMEM);

    pre_kernel<<<NROWS + (KGLOB / 64) * (OUTFEAT / 64), 256>>>(
        input, dims, thr, lut);

    dim3 grid(OUTFEAT / TO, NROWS / TN);
    agg_kernel<<<grid, THREADS, AGG_SMEM>>>(out);
}

// round 16
// speedup vs baseline: 1.4978x; 1.0067x over previous
#include <cuda_runtime.h>
#include <cuda_fp16.h>
#include <cstdint>

// Problem constants
#define NROWS   4096
#define INFEAT  4096
#define OUTFEAT 4096
#define NCODE   256
#define KLEAF   16
#define KGLOB   4096
// Aggregation tiling
#define TO      128
#define TN      128
#define THREADS 256
#define CCH     8
#define NCHUNK  (NCODE / CCH)      // 32
#define BUFB    32768              // 128 idx rows x 256 B
#define NBUF    3
#define MBAR_OFF (NBUF * BUFB)
#define AGG_SMEM (MBAR_OFF + 64)   // 96 KB + mbarriers
// Unequal tiling: 888 full tiles (3 exact waves on 296 occ-2 slots) +
// 136 tiles split into 272 half-tiles for the tail wave.
#define NFULL   888
#define NTASKS  (NFULL + 2 * (1024 - NFULL))   // 1160

// Static device scratch
__device__ __align__(16) unsigned char g_codes[NROWS * NCODE];          // 1 MB
__device__ __align__(16) __half        g_lutT[(size_t)KGLOB * OUTFEAT]; // 32 MB [k][o]

// ---------------------------------------------------------------- helpers
__device__ __forceinline__ uint32_t smem_u32(const void* p) {
    uint32_t a;
    asm("{ .reg .u64 t; cvta.to.shared.u64 t, %1; cvt.u32.u64 %0, t; }"
        : "=r"(a) : "l"(p));
    return a;
}
__device__ __forceinline__ void cp_async16(uint32_t s, const void* g) {
    asm volatile("cp.async.cg.shared.global [%0], [%1], 16;"
                 :: "r"(s), "l"(g) : "memory");
}
__device__ __forceinline__ void cp_arrive_noinc(uint32_t mbar) {
    asm volatile("cp.async.mbarrier.arrive.noinc.shared::cta.b64 [%0];"
                 :: "r"(mbar) : "memory");
}
__device__ __forceinline__ void mbar_init(uint32_t a, uint32_t n) {
    asm volatile("mbarrier.init.shared.b64 [%0], %1;" :: "r"(a), "r"(n) : "memory");
}
__device__ __forceinline__ void mbar_arrive(uint32_t a) {
    asm volatile("mbarrier.arrive.shared.b64 _, [%0];" :: "r"(a) : "memory");
}
__device__ __forceinline__ void mbar_wait(uint32_t mbar, uint32_t parity) {
    uint32_t done;
    asm volatile(
        "{ .reg .pred p;"
        "mbarrier.try_wait.parity.acquire.cta.shared::cta.b64 p, [%1], %2;"
        "selp.b32 %0,1,0,p; }" : "=r"(done) : "r"(mbar), "r"(parity) : "memory");
    if (!done) {
        asm volatile(
            "{ .reg .pred P1; WL_%=:"
            "mbarrier.try_wait.parity.acquire.cta.shared::cta.b64 P1, [%0], %1, 0x989680;"
            "@P1 bra.uni WD_%=; bra.uni WL_%=; WD_%=: }"
            :: "r"(mbar), "r"(parity) : "memory");
    }
}

// ---------------------------------------------------------------- pre
// Fused encode + transpose/convert (independent halves of one grid).
__global__ void __launch_bounds__(256) pre_kernel(
    const float* __restrict__ input,
    const int*   __restrict__ dims,
    const float* __restrict__ thr,
    const float* __restrict__ lut)
{
    __shared__ __half tile[64][72];
    const int tid = threadIdx.x;

    if (blockIdx.x < NROWS) {
        const int n = blockIdx.x;
        const int c = tid;
        const int4 d4 = *reinterpret_cast<const int4*>(dims + c * 4);
        const float* row = input + (size_t)n * INFEAT;
        const float x0 = __ldg(row + d4.x);
        const float x1 = __ldg(row + d4.y);
        const float x2 = __ldg(row + d4.z);
        const float x3 = __ldg(row + d4.w);
        const float* t = thr + c * 15;
        int i = 1;
        i = 2 * i + (x0 > __ldg(t + i - 1) ? 1 : 0);
        i = 2 * i + (x1 > __ldg(t + i - 1) ? 1 : 0);
        i = 2 * i + (x2 > __ldg(t + i - 1) ? 1 : 0);
        i = 2 * i + (x3 > __ldg(t + i - 1) ? 1 : 0);
        g_codes[n * NCODE + c] = (unsigned char)(i - 16);
    } else {
        const int linear = blockIdx.x - NROWS;      // 0..4095
        const int k0 = (linear >> 6) * 64;
        const int o0 = (linear & 63) * 64;

#pragma unroll
        for (int j = 0; j < 4; ++j) {
            const int flat = j * 256 + tid;
            const int o  = flat >> 4;
            const int kq = flat & 15;
            const float4 v = __ldg(reinterpret_cast<const float4*>(
                lut + (size_t)(o0 + o) * KGLOB + k0 + kq * 4));
            tile[kq * 4 + 0][o] = __float2half(v.x);
            tile[kq * 4 + 1][o] = __float2half(v.y);
            tile[kq * 4 + 2][o] = __float2half(v.z);
            tile[kq * 4 + 3][o] = __float2half(v.w);
        }
        __syncthreads();
#pragma unroll
        for (int j = 0; j < 2; ++j) {
            const int flat = j * 256 + tid;
            const int k  = flat >> 3;
            const int oq = flat & 7;
            const uint4 v = *reinterpret_cast<const uint4*>(&tile[k][oq * 8]);
            *reinterpret_cast<uint4*>(
                g_lutT + (size_t)(k0 + k) * OUTFEAT + o0 + oq * 8) = v;
        }
    }
}

// ---------------------------------------------------------------- agg tile
// R15 pipeline, parametrized by rows-per-warp (16 = full tile, 8 = half).
template <int TROWS>
__device__ __forceinline__ void agg_tile(
    uint32_t sb, uint32_t MB, int o0, int n0,
    int tid, int warp, int lane, float* __restrict__ out)
{
    const int rowbase = n0 + warp * TROWS;
    const uint32_t lane_byte = (uint32_t)lane * 8;

    float acc[TROWS][4];
#pragma unroll
    for (int t = 0; t < TROWS; ++t)
#pragma unroll
        for (int j = 0; j < 4; ++j) acc[t][j] = 0.0f;

#define STAGE(ch, bufbase) do {                                                \
    const int _c0k = (ch) * CCH * KLEAF;                                       \
    _Pragma("unroll")                                                          \
    for (int _i = 0; _i < 8; ++_i) {                                           \
        const int _flat = _i * THREADS + tid;      /* 0..2047 */               \
        const int _idx  = _flat >> 4;                                          \
        const int _pos  = _flat & 15;                                          \
        cp_async16((bufbase) + (uint32_t)_flat * 16,                           \
                   g_lutT + (size_t)(_c0k + _idx) * OUTFEAT + o0 + _pos * 8);  \
    }                                                                          \
} while (0)

    // Prologue: stage chunks 0..2
#pragma unroll
    for (int p = 0; p < NBUF; ++p) {
        STAGE(p, sb + (uint32_t)p * BUFB);
        cp_arrive_noinc(MB + p * 8);
    }

    for (int ch = 0; ch < NCHUNK; ++ch) {
        const int b  = ch % NBUF;
        const uint32_t ph = (uint32_t)(ch / NBUF) & 1u;

        mbar_wait(MB + b * 8, ph);   // full[b]

        const uint32_t gbase = sb + (uint32_t)b * BUFB + lane_byte;
        const int cb0 = ch * CCH;

#pragma unroll
        for (int t = 0; t < TROWS; ++t) {
            const int row = rowbase + t;
            const uint2 cw = *reinterpret_cast<const uint2*>(
                g_codes + (size_t)row * NCODE + cb0);   // warp-uniform

            uint2 v[8];
#pragma unroll
            for (int cc = 0; cc < 8; ++cc) {
                const unsigned int w = (cc < 4) ? cw.x : cw.y;
                const unsigned int c256 =
                    __byte_perm(w, 0u, 0x4404u | (((unsigned)cc & 3u) << 4));
                asm volatile("ld.shared.v2.u32 {%0,%1}, [%2];"
                             : "=r"(v[cc].x), "=r"(v[cc].y)
                             : "r"(gbase + (uint32_t)cc * 4096u + c256));
            }
#define H2X(i) (*reinterpret_cast<const __half2*>(&v[i].x))
#define H2Y(i) (*reinterpret_cast<const __half2*>(&v[i].y))
            const __half2 p0 = __hadd2(H2X(0), H2X(1));
            const __half2 p1 = __hadd2(H2X(2), H2X(3));
            const __half2 p2 = __hadd2(H2X(4), H2X(5));
            const __half2 p3 = __hadd2(H2X(6), H2X(7));
            const __half2 q0 = __hadd2(H2Y(0), H2Y(1));
            const __half2 q1 = __hadd2(H2Y(2), H2Y(3));
            const __half2 q2 = __hadd2(H2Y(4), H2Y(5));
            const __half2 q3 = __hadd2(H2Y(6), H2Y(7));
            const __half2 h01 = __hadd2(__hadd2(p0, p1), __hadd2(p2, p3));
            const __half2 h23 = __hadd2(__hadd2(q0, q1), __hadd2(q2, q3));
#undef H2X
#undef H2Y
            const float2 f0 = __half22float2(h01);
            const float2 f1 = __half22float2(h23);
            acc[t][0] += f0.x;
            acc[t][1] += f0.y;
            acc[t][2] += f1.x;
            acc[t][3] += f1.y;
        }

        if (lane == 0) mbar_arrive(MB + 24 + b * 8);   // release buffer b

        // Deferred refill for buffer b(ch-1) -> chunk ch-1+NBUF
        const int pc = ch - 1;
        if (pc >= 0 && pc + NBUF < NCHUNK) {
            const int pb = pc % NBUF;
            const uint32_t pph = (uint32_t)(pc / NBUF) & 1u;
            mbar_wait(MB + 24 + pb * 8, pph);          // empty[pb]
            STAGE(pc + NBUF, sb + (uint32_t)pb * BUFB);
            cp_arrive_noinc(MB + pb * 8);
        }
    }
#undef STAGE

#pragma unroll
    for (int t = 0; t < TROWS; ++t) {
        float4 v;
        v.x = acc[t][0]; v.y = acc[t][1]; v.z = acc[t][2]; v.w = acc[t][3];
        *reinterpret_cast<float4*>(
            out + (size_t)(rowbase + t) * OUTFEAT + o0 + 4 * lane) = v;
    }
}

// ---------------------------------------------------------------- agg
// Unequal tiling: bid < 888 -> full tile (TN=128); else half tiles (TN=64)
// of tiles 888..1023, two blocks each. CTA raster ~ bid order puts the
// half tiles in the final wave, halving the tail.
__global__ void __launch_bounds__(THREADS, 2) agg_kernel(float* __restrict__ out)
{
    extern __shared__ __align__(16) char smem[];
    const uint32_t sb = smem_u32(smem);
    const uint32_t MB = sb + MBAR_OFF;   // full[i]=MB+8i, empty[i]=MB+24+8i

    const int tid  = threadIdx.x;
    const int warp = tid >> 5;
    const int lane = tid & 31;
    const int bid  = blockIdx.x;

    if (tid == 0) {
#pragma unroll
        for (int i = 0; i < NBUF; ++i) {
            mbar_init(MB + i * 8, THREADS);   // full: noinc cp.async arrivals
            mbar_init(MB + 24 + i * 8, 8);    // empty: one arrive per warp
        }
    }
    __syncthreads();

    if (bid < NFULL) {
        const int t = bid;                       // tile id 0..887
        const int o0 = (t & 31) * TO;
        const int n0 = (t >> 5) * TN;
        agg_tile<16>(sb, MB, o0, n0, tid, warp, lane, out);
    } else {
        const int j = (bid - NFULL) >> 1;        // split tile index 0..135
        const int h = (bid - NFULL) & 1;         // which half
        const int t = NFULL + j;                 // tile id 888..1023
        const int o0 = (t & 31) * TO;
        const int n0 = (t >> 5) * TN + h * 64;
        agg_tile<8>(sb, MB, o0, n0, tid, warp, lane, out);
    }
}

// ---------------------------------------------------------------- launch
extern "C" void kernel_launch(void* const* d_in, const int* in_sizes, int n_in,
                              void* d_out, int out_size)
{
    const float* input = (const float*)d_in[0];
    const int*   dims  = (const int*)  d_in[1];
    const float* thr   = (const float*)d_in[3];
    const float* lut   = (const float*)d_in[5];
    float*       out   = (float*)d_out;
    (void)in_sizes; (void)n_in; (void)out_size;

    cudaFuncSetAttribute(agg_kernel,
                         cudaFuncAttributeMaxDynamicSharedMemorySize, AGG_SMEM);

    pre_kernel<<<NROWS + (KGLOB / 64) * (OUTFEAT / 64), 256>>>(
        input, dims, thr, lut);

    agg_kernel<<<NTASKS, THREADS, AGG_SMEM>>>(out);
}